// round 2
// baseline (speedup 1.0000x reference)
#include <cuda_runtime.h>
#include <cstdint>
#include <cmath>

// ---------------------------------------------------------------------------
// WeightedRankNet: gather 5 columns from a 1M x 136 f32 table at 1M random
// indices, BM25 + link-weight scoring, plus bit-exact JAX Threefry-2x32
// uniform noise. JAX >= 0.5 default: threefry_partitionable=True, i.e.
// bits[i] = out0 ^ out1 of threefry2x32(key=(0,1), counter=(i>>32, i&0xffffffff)).
// ---------------------------------------------------------------------------

#define N_FEAT        136
#define COL_DOCLEN    14
#define COL_WHOLE_LEN 16
#define COL_TF        24
#define COL_INLINK    127
#define COL_OUTLINK   128
#define COL_PAGERANK  129

#define SUM_BLOCKS 1024
#define SUM_TPB    256

__device__ float g_partials[SUM_BLOCKS];
__device__ float g_avg;

// ---- pass 1: deterministic partial sums of column 16 ----------------------
__global__ void col16_sum_kernel(const float* __restrict__ gf, int n_docs) {
    __shared__ float sdata[SUM_TPB];
    float s = 0.0f;
    for (int i = blockIdx.x * blockDim.x + threadIdx.x; i < n_docs;
         i += gridDim.x * blockDim.x) {
        s += gf[(long long)i * N_FEAT + COL_WHOLE_LEN];
    }
    sdata[threadIdx.x] = s;
    __syncthreads();
    for (int k = SUM_TPB / 2; k > 0; k >>= 1) {
        if (threadIdx.x < k) sdata[threadIdx.x] += sdata[threadIdx.x + k];
        __syncthreads();
    }
    if (threadIdx.x == 0) g_partials[blockIdx.x] = sdata[0];
}

// ---- pass 2: fold partials into the mean -----------------------------------
__global__ void finalize_avg_kernel(int n_docs) {
    __shared__ float sdata[SUM_BLOCKS];
    sdata[threadIdx.x] = g_partials[threadIdx.x];
    __syncthreads();
    for (int k = SUM_BLOCKS / 2; k > 0; k >>= 1) {
        if (threadIdx.x < k) sdata[threadIdx.x] += sdata[threadIdx.x + k];
        __syncthreads();
    }
    if (threadIdx.x == 0) g_avg = sdata[0] / (float)n_docs;
}

// ---- Threefry-2x32 ---------------------------------------------------------
__device__ __forceinline__ uint32_t rotl32(uint32_t x, uint32_t r) {
    return __funnelshift_l(x, x, r);
}

// ---- main fused kernel ------------------------------------------------------
__global__ void __launch_bounds__(256)
rank_kernel(const int* __restrict__ idxs,
            const float* __restrict__ gf,
            const float* __restrict__ s_k1,
            const float* __restrict__ s_b,
            const float* __restrict__ s_bw,
            const float* __restrict__ s_pr,
            const float* __restrict__ s_in,
            const float* __restrict__ s_out,
            const float* __restrict__ s_fr,
            float* __restrict__ out,
            int batch, float idf)
{
    int i = blockIdx.x * blockDim.x + threadIdx.x;
    if (i >= batch) return;

    // Issue gather loads EARLY so the Threefry ALU overlaps the DRAM latency.
    long long row = (long long)__ldg(idxs + i) * (long long)N_FEAT;
    float dl  = __ldg(gf + row + COL_DOCLEN);
    float tf  = __ldg(gf + row + COL_TF);
    float inl = __ldg(gf + row + COL_INLINK);
    float oul = __ldg(gf + row + COL_OUTLINK);
    float pr  = __ldg(gf + row + COL_PAGERANK);

    // Threefry-2x32-20, key = (0, 1), partitionable counters:
    // x0 = uint32(i >> 32) = 0, x1 = uint32(i). Output = out0 ^ out1.
    uint32_t x0 = 0u;
    uint32_t x1 = (uint32_t)i;

    const uint32_t ks0 = 0u;
    const uint32_t ks1 = 1u;
    const uint32_t ks2 = 0x1BD11BDBu;  // 0 ^ 1 ^ 0x1BD11BDA

    x0 += ks0; x1 += ks1;
#define TF_R(r) { x0 += x1; x1 = rotl32(x1, (r)); x1 ^= x0; }
    TF_R(13) TF_R(15) TF_R(26) TF_R(6)
    x0 += ks1; x1 += ks2 + 1u;
    TF_R(17) TF_R(29) TF_R(16) TF_R(24)
    x0 += ks2; x1 += ks0 + 2u;
    TF_R(13) TF_R(15) TF_R(26) TF_R(6)
    x0 += ks0; x1 += ks1 + 3u;
    TF_R(17) TF_R(29) TF_R(16) TF_R(24)
    x0 += ks1; x1 += ks2 + 4u;
    TF_R(13) TF_R(15) TF_R(26) TF_R(6)
    x0 += ks2; x1 += ks0 + 5u;
#undef TF_R

    uint32_t bits = x0 ^ x1;

    // JAX uniform: (bits >> 9) | 0x3f800000 reinterpreted as f32, minus 1,
    // then max(0, .).
    float u = __uint_as_float((bits >> 9) | 0x3f800000u) - 1.0f;
    u = fmaxf(0.0f, u);

    float k1  = __ldg(s_k1);
    float b   = __ldg(s_b);
    float bw  = __ldg(s_bw);
    float prw = __ldg(s_pr);
    float inw = __ldg(s_in);
    float otw = __ldg(s_out);
    float frw = __ldg(s_fr);
    float avg = g_avg;

    float num  = tf * (k1 + 1.0f);
    float den  = tf + k1 * (1.0f - b + b * (dl / avg));
    float bm25 = idf * (num / den);
    float pg   = prw * pr + inw * inl + otw * oul;
    out[i] = bw * bm25 + pg + u * frw;
}

// ---------------------------------------------------------------------------
extern "C" void kernel_launch(void* const* d_in, const int* in_sizes, int n_in,
                              void* d_out, int out_size)
{
    const int*   idxs = (const int*)d_in[0];
    const float* gf   = (const float*)d_in[1];
    const float* k1   = (const float*)d_in[2];
    const float* b    = (const float*)d_in[3];
    const float* bw   = (const float*)d_in[4];
    const float* prw  = (const float*)d_in[5];
    const float* inw  = (const float*)d_in[6];
    const float* outw = (const float*)d_in[7];
    const float* frw  = (const float*)d_in[8];
    float* out = (float*)d_out;

    int batch  = in_sizes[0];
    int n_docs = in_sizes[1] / N_FEAT;

    // idf replicated in the reference's exact f32 operation order:
    // log((total - num + 0.5) / (num + 0.5) + 1.0) with num == total.
    float total = (float)n_docs;
    float idf = logf(((total - total) + 0.5f) / (total + 0.5f) + 1.0f);

    col16_sum_kernel<<<SUM_BLOCKS, SUM_TPB>>>(gf, n_docs);
    finalize_avg_kernel<<<1, SUM_BLOCKS>>>(n_docs);

    int tpb = 256;
    int blocks = (batch + tpb - 1) / tpb;
    rank_kernel<<<blocks, tpb>>>(idxs, gf, k1, b, bw, prw, inw, outw, frw,
                                 out, batch, idf);
}